// round 1
// baseline (speedup 1.0000x reference)
#include <cuda_runtime.h>
#include <cstdint>

#define BATCH 4
#define SEQ   2048
#define DMODEL 1024
#define NHEAD 16
#define DHEAD 64
#define MTOT  (BATCH*SEQ)   // 8192

// ---------------- scratch (static device globals; no runtime alloc) ----------
__device__ float g_Q[BATCH*NHEAD*SEQ*DHEAD];   // 32 MB, [B,H,S,DH]
__device__ float g_K[BATCH*NHEAD*SEQ*DHEAD];
__device__ float g_V[BATCH*NHEAD*SEQ*DHEAD];
__device__ float g_ctx[MTOT*DMODEL];           // [B*S, D]
__device__ float g_h[MTOT*DMODEL];             // O-proj output

// ---------------- helpers ----------------------------------------------------
__device__ __forceinline__ float to_tf32(float x) {
    asm("cvt.rna.tf32.f32 %0, %0;" : "+f"(x));
    return x;
}

__device__ __forceinline__ void mma_tf32(float c[4], const uint32_t a[4], const uint32_t b[2]) {
    asm volatile(
        "mma.sync.aligned.m16n8k8.row.col.f32.tf32.tf32.f32 "
        "{%0,%1,%2,%3}, {%4,%5,%6,%7}, {%8,%9}, {%0,%1,%2,%3};"
        : "+f"(c[0]), "+f"(c[1]), "+f"(c[2]), "+f"(c[3])
        : "r"(a[0]), "r"(a[1]), "r"(a[2]), "r"(a[3]), "r"(b[0]), "r"(b[1]));
}

// ---------------- GEMM: out = A[M,K] @ W[K,N] + bias --------------------------
// BM=128, BN=64, BK=32. 256 threads = 8 warps in a 4(m) x 2(n) grid.
// Warp tile 32x32 = 2 m-frags (16) x 4 n-frags (8). tf32 mma, fp32 accum.
#define BM 128
#define BN 64
#define BK 32

__global__ __launch_bounds__(256) void gemm_kernel(
    const float* __restrict__ A, const float* __restrict__ W,
    const float* __restrict__ bias, float* __restrict__ out, int split_heads)
{
    __shared__ float Asm[BM][BK + 4];   // stride 36: conflict-free a-frag loads
    __shared__ float Bsm[BK][BN + 4];   // stride 68

    const int tid  = threadIdx.x;
    const int lane = tid & 31;
    const int warp = tid >> 5;
    const int wm   = warp >> 1;         // 0..3
    const int wn   = warp & 1;          // 0..1
    const int m0   = blockIdx.y * BM;
    const int n0   = blockIdx.x * BN;

    float acc[2][4][4];
#pragma unroll
    for (int im = 0; im < 2; im++)
#pragma unroll
        for (int in = 0; in < 4; in++)
#pragma unroll
            for (int k = 0; k < 4; k++) acc[im][in][k] = 0.f;

    for (int k0 = 0; k0 < DMODEL; k0 += BK) {
        // load A tile 128x32: 1024 float4 / 256 thr = 4 each
#pragma unroll
        for (int i = 0; i < 4; i++) {
            int idx = tid + i * 256;            // 0..1023
            int r = idx >> 3, c4 = (idx & 7) * 4;
            float4 v = *(const float4*)(A + (size_t)(m0 + r) * DMODEL + k0 + c4);
            Asm[r][c4 + 0] = to_tf32(v.x);
            Asm[r][c4 + 1] = to_tf32(v.y);
            Asm[r][c4 + 2] = to_tf32(v.z);
            Asm[r][c4 + 3] = to_tf32(v.w);
        }
        // load B tile 32x64: 512 float4 / 256 thr = 2 each
#pragma unroll
        for (int i = 0; i < 2; i++) {
            int idx = tid + i * 256;            // 0..511
            int r = idx >> 4, c4 = (idx & 15) * 4;
            float4 v = *(const float4*)(W + (size_t)(k0 + r) * DMODEL + n0 + c4);
            Bsm[r][c4 + 0] = to_tf32(v.x);
            Bsm[r][c4 + 1] = to_tf32(v.y);
            Bsm[r][c4 + 2] = to_tf32(v.z);
            Bsm[r][c4 + 3] = to_tf32(v.w);
        }
        __syncthreads();

#pragma unroll
        for (int ks = 0; ks < BK / 8; ks++) {
            const int ck = ks * 8 + (lane & 3);
            uint32_t afr[2][4];
#pragma unroll
            for (int im = 0; im < 2; im++) {
                int r = wm * 32 + im * 16 + (lane >> 2);
                afr[im][0] = __float_as_uint(Asm[r][ck]);
                afr[im][1] = __float_as_uint(Asm[r + 8][ck]);
                afr[im][2] = __float_as_uint(Asm[r][ck + 4]);
                afr[im][3] = __float_as_uint(Asm[r + 8][ck + 4]);
            }
            uint32_t bfr[4][2];
#pragma unroll
            for (int in = 0; in < 4; in++) {
                int c = wn * 32 + in * 8 + (lane >> 2);
                bfr[in][0] = __float_as_uint(Bsm[ks * 8 + (lane & 3)][c]);
                bfr[in][1] = __float_as_uint(Bsm[ks * 8 + (lane & 3) + 4][c]);
            }
#pragma unroll
            for (int im = 0; im < 2; im++)
#pragma unroll
                for (int in = 0; in < 4; in++)
                    mma_tf32(acc[im][in], afr[im], bfr[in]);
        }
        __syncthreads();
    }

    // epilogue: + bias, store (optionally head-split to [B,H,S,DH])
#pragma unroll
    for (int im = 0; im < 2; im++) {
#pragma unroll
        for (int in = 0; in < 4; in++) {
            int r = m0 + wm * 32 + im * 16 + (lane >> 2);
            int c = n0 + wn * 32 + in * 8 + 2 * (lane & 3);
            float b0 = bias[c], b1 = bias[c + 1];
            float2 v0 = make_float2(acc[im][in][0] + b0, acc[im][in][1] + b1);
            float2 v1 = make_float2(acc[im][in][2] + b0, acc[im][in][3] + b1);
            if (split_heads) {
                int b = r >> 11, s = r & (SEQ - 1);
                int h = c >> 6,  d = c & (DHEAD - 1);
                size_t base = (((size_t)(b * NHEAD + h) * SEQ + s) * DHEAD + d);
                *(float2*)(out + base) = v0;
                *(float2*)(out + base + 8 * DHEAD) = v1;   // row r+8 -> s+8
            } else {
                size_t base = (size_t)r * DMODEL + c;
                *(float2*)(out + base) = v0;
                *(float2*)(out + base + (size_t)8 * DMODEL) = v1;
            }
        }
    }
}

// ---------------- flash attention --------------------------------------------
// One CTA: (b, h, 64-query tile). 256 threads = 8 warps in 4(m) x 2(n).
// Loop over 32 key tiles of 64; tf32 mma for QK^T and PV; online softmax in smem.
#define LDW 68   // smem row stride (64 + 4 pad)

__global__ __launch_bounds__(256) void attn_kernel(
    const float* __restrict__ Q, const float* __restrict__ K,
    const float* __restrict__ V, const float* __restrict__ mask,
    float* __restrict__ ctx)
{
    extern __shared__ float sm[];
    float* Qs  = sm;                    // [64][68]
    float* Ks  = sm + 64 * LDW;
    float* Vs  = sm + 2 * 64 * LDW;
    float* Ss  = sm + 3 * 64 * LDW;     // scores, then P
    float* msk = sm + 4 * 64 * LDW;     // [64]
    float* msm = msk + 64;
    float* lsm = msm + 64;
    float* alp = lsm + 64;

    const int tid  = threadIdx.x;
    const int lane = tid & 31;
    const int warp = tid >> 5;
    const int wm   = warp >> 1;   // 0..3: 16 rows each
    const int wn   = warp & 1;    // 0..1: 32 cols each

    const int q0 = blockIdx.x * 64;
    const int h  = blockIdx.y;
    const int b  = blockIdx.z;

    const float* Qp = Q + (((size_t)(b * NHEAD + h) * SEQ + q0) * DHEAD);
    const float* Kp = K + ((size_t)(b * NHEAD + h) * SEQ) * DHEAD;
    const float* Vp = V + ((size_t)(b * NHEAD + h) * SEQ) * DHEAD;

    // load Q tile (scale 1/sqrt(64)=0.125 folded in), tf32-converted
#pragma unroll
    for (int i = 0; i < 4; i++) {
        int idx = tid + i * 256;           // 0..1023 (64 rows x 16 float4)
        int r = idx >> 4, c4 = (idx & 15) * 4;
        float4 v = *(const float4*)(Qp + (size_t)r * DHEAD + c4);
        Qs[r * LDW + c4 + 0] = to_tf32(v.x * 0.125f);
        Qs[r * LDW + c4 + 1] = to_tf32(v.y * 0.125f);
        Qs[r * LDW + c4 + 2] = to_tf32(v.z * 0.125f);
        Qs[r * LDW + c4 + 3] = to_tf32(v.w * 0.125f);
    }
    if (tid < 64) { msm[tid] = -1e30f; lsm[tid] = 0.f; }

    float oacc[4][4];
#pragma unroll
    for (int in = 0; in < 4; in++)
#pragma unroll
        for (int k = 0; k < 4; k++) oacc[in][k] = 0.f;

    for (int kt = 0; kt < SEQ / 64; kt++) {
        const int key0 = kt * 64;
        // load K,V tiles (tf32) + mask slice
#pragma unroll
        for (int i = 0; i < 4; i++) {
            int idx = tid + i * 256;
            int r = idx >> 4, c4 = (idx & 15) * 4;
            float4 kv = *(const float4*)(Kp + (size_t)(key0 + r) * DHEAD + c4);
            Ks[r * LDW + c4 + 0] = to_tf32(kv.x);
            Ks[r * LDW + c4 + 1] = to_tf32(kv.y);
            Ks[r * LDW + c4 + 2] = to_tf32(kv.z);
            Ks[r * LDW + c4 + 3] = to_tf32(kv.w);
            float4 vv = *(const float4*)(Vp + (size_t)(key0 + r) * DHEAD + c4);
            Vs[r * LDW + c4 + 0] = to_tf32(vv.x);
            Vs[r * LDW + c4 + 1] = to_tf32(vv.y);
            Vs[r * LDW + c4 + 2] = to_tf32(vv.z);
            Vs[r * LDW + c4 + 3] = to_tf32(vv.w);
        }
        if (tid < 64) msk[tid] = mask[(size_t)b * SEQ + key0 + tid];
        __syncthreads();

        // S = Q @ K^T  (64x64, k=DH=64)
        float sacc[4][4];
#pragma unroll
        for (int in = 0; in < 4; in++)
#pragma unroll
            for (int k = 0; k < 4; k++) sacc[in][k] = 0.f;

#pragma unroll
        for (int ks = 0; ks < 8; ks++) {
            const int ck = ks * 8 + (lane & 3);
            const int r  = wm * 16 + (lane >> 2);
            uint32_t af[4] = {
                __float_as_uint(Qs[r * LDW + ck]),
                __float_as_uint(Qs[(r + 8) * LDW + ck]),
                __float_as_uint(Qs[r * LDW + ck + 4]),
                __float_as_uint(Qs[(r + 8) * LDW + ck + 4]) };
#pragma unroll
            for (int in = 0; in < 4; in++) {
                int n = wn * 32 + in * 8 + (lane >> 2);
                uint32_t bf[2] = {
                    __float_as_uint(Ks[n * LDW + ck]),       // (k=dh, n=key) = K[key][dh]
                    __float_as_uint(Ks[n * LDW + ck + 4]) };
                mma_tf32(sacc[in], af, bf);
            }
        }
        // scatter S frags to smem
        {
            const int r = wm * 16 + (lane >> 2);
#pragma unroll
            for (int in = 0; in < 4; in++) {
                int c = wn * 32 + in * 8 + 2 * (lane & 3);
                Ss[r * LDW + c]           = sacc[in][0];
                Ss[r * LDW + c + 1]       = sacc[in][1];
                Ss[(r + 8) * LDW + c]     = sacc[in][2];
                Ss[(r + 8) * LDW + c + 1] = sacc[in][3];
            }
        }
        __syncthreads();

        // online softmax (one thread per query row)
        if (tid < 64) {
            const int r = tid;
            float mo = msm[r];
            float mx = mo;
#pragma unroll 8
            for (int j = 0; j < 64; j++) mx = fmaxf(mx, Ss[r * LDW + j] + msk[j]);
            float al = __expf(mo - mx);
            float l  = lsm[r] * al;
#pragma unroll 8
            for (int j = 0; j < 64; j++) {
                float p = __expf(Ss[r * LDW + j] + msk[j] - mx);
                l += p;
                Ss[r * LDW + j] = to_tf32(p);
            }
            msm[r] = mx; lsm[r] = l; alp[r] = al;
        }
        __syncthreads();

        // rescale O accumulators
        {
            const int r = wm * 16 + (lane >> 2);
            float a1 = alp[r], a2 = alp[r + 8];
#pragma unroll
            for (int in = 0; in < 4; in++) {
                oacc[in][0] *= a1; oacc[in][1] *= a1;
                oacc[in][2] *= a2; oacc[in][3] *= a2;
            }
        }
        // O += P @ V   (P: 64x64 over keys, V: 64(key) x 64(dh))
#pragma unroll
        for (int ks = 0; ks < 8; ks++) {
            const int ck = ks * 8 + (lane & 3);
            const int r  = wm * 16 + (lane >> 2);
            uint32_t af[4] = {
                __float_as_uint(Ss[r * LDW + ck]),
                __float_as_uint(Ss[(r + 8) * LDW + ck]),
                __float_as_uint(Ss[r * LDW + ck + 4]),
                __float_as_uint(Ss[(r + 8) * LDW + ck + 4]) };
#pragma unroll
            for (int in = 0; in < 4; in++) {
                int n = wn * 32 + in * 8 + (lane >> 2);
                uint32_t bf[2] = {
                    __float_as_uint(Vs[ck * LDW + n]),       // (k=key, n=dh)
                    __float_as_uint(Vs[(ck + 4) * LDW + n]) };
                mma_tf32(oacc[in], af, bf);
            }
        }
        __syncthreads();
    }

    // finalize: /l, write ctx [B,S,D] (d = h*64 + col)
    {
        const int r = wm * 16 + (lane >> 2);
        float il1 = 1.f / lsm[r];
        float il2 = 1.f / lsm[r + 8];
#pragma unroll
        for (int in = 0; in < 4; in++) {
            int c = wn * 32 + in * 8 + 2 * (lane & 3);
            size_t base = ((size_t)b * SEQ + q0 + r) * DMODEL + h * DHEAD + c;
            float2 v0 = make_float2(oacc[in][0] * il1, oacc[in][1] * il1);
            float2 v1 = make_float2(oacc[in][2] * il2, oacc[in][3] * il2);
            *(float2*)(ctx + base) = v0;
            *(float2*)(ctx + base + (size_t)8 * DMODEL) = v1;
        }
    }
}

// ---------------- residual + LayerNorm ---------------------------------------
__global__ __launch_bounds__(256) void ln_kernel(
    const float* __restrict__ hbuf, const float* __restrict__ x,
    const float* __restrict__ gamma, const float* __restrict__ beta,
    float* __restrict__ out)
{
    const int row = blockIdx.x;
    const int tid = threadIdx.x;
    const int lane = tid & 31, warp = tid >> 5;

    const float4* hp = (const float4*)(hbuf + (size_t)row * DMODEL);
    const float4* xp = (const float4*)(x + (size_t)row * DMODEL);
    float4 hv = hp[tid], xv = xp[tid];
    float4 y = make_float4(hv.x + xv.x, hv.y + xv.y, hv.z + xv.z, hv.w + xv.w);

    float s  = y.x + y.y + y.z + y.w;
    float sq = y.x * y.x + y.y * y.y + y.z * y.z + y.w * y.w;
#pragma unroll
    for (int o = 16; o; o >>= 1) {
        s  += __shfl_xor_sync(0xffffffffu, s, o);
        sq += __shfl_xor_sync(0xffffffffu, sq, o);
    }
    __shared__ float ss[8], ssq[8];
    if (lane == 0) { ss[warp] = s; ssq[warp] = sq; }
    __syncthreads();
    if (warp == 0) {
        s  = (lane < 8) ? ss[lane]  : 0.f;
        sq = (lane < 8) ? ssq[lane] : 0.f;
#pragma unroll
        for (int o = 4; o; o >>= 1) {
            s  += __shfl_xor_sync(0xffffffffu, s, o);
            sq += __shfl_xor_sync(0xffffffffu, sq, o);
        }
        if (lane == 0) { ss[0] = s; ssq[0] = sq; }
    }
    __syncthreads();
    s = ss[0]; sq = ssq[0];

    const float mu   = s * (1.f / DMODEL);
    const float var  = sq * (1.f / DMODEL) - mu * mu;
    const float rstd = rsqrtf(var + 1e-12f);

    float4 g = ((const float4*)gamma)[tid];
    float4 bt = ((const float4*)beta)[tid];
    float4 o;
    o.x = (y.x - mu) * rstd * g.x + bt.x;
    o.y = (y.y - mu) * rstd * g.y + bt.y;
    o.z = (y.z - mu) * rstd * g.z + bt.z;
    o.w = (y.w - mu) * rstd * g.w + bt.w;
    ((float4*)(out + (size_t)row * DMODEL))[tid] = o;
}

// ---------------- launch ------------------------------------------------------
extern "C" void kernel_launch(void* const* d_in, const int* in_sizes, int n_in,
                              void* d_out, int out_size)
{
    const float* x    = (const float*)d_in[0];
    const float* mask = (const float*)d_in[1];
    const float* Wq   = (const float*)d_in[2];
    const float* bq   = (const float*)d_in[3];
    const float* Wk   = (const float*)d_in[4];
    const float* bk   = (const float*)d_in[5];
    const float* Wv   = (const float*)d_in[6];
    const float* bv   = (const float*)d_in[7];
    const float* Wo   = (const float*)d_in[8];
    const float* bo   = (const float*)d_in[9];
    const float* gam  = (const float*)d_in[10];
    const float* bet  = (const float*)d_in[11];
    float* out = (float*)d_out;

    float *pQ, *pK, *pV, *pC, *pH;
    cudaGetSymbolAddress((void**)&pQ, g_Q);
    cudaGetSymbolAddress((void**)&pK, g_K);
    cudaGetSymbolAddress((void**)&pV, g_V);
    cudaGetSymbolAddress((void**)&pC, g_ctx);
    cudaGetSymbolAddress((void**)&pH, g_h);

    dim3 ggrid(DMODEL / BN, MTOT / BM);   // (16, 64)
    gemm_kernel<<<ggrid, 256>>>(x, Wq, bq, pQ, 1);
    gemm_kernel<<<ggrid, 256>>>(x, Wk, bk, pK, 1);
    gemm_kernel<<<ggrid, 256>>>(x, Wv, bv, pV, 1);

    const int smem_bytes = (4 * 64 * LDW + 4 * 64) * (int)sizeof(float); // 70656
    cudaFuncSetAttribute(attn_kernel, cudaFuncAttributeMaxDynamicSharedMemorySize, smem_bytes);
    attn_kernel<<<dim3(SEQ / 64, NHEAD, BATCH), 256, smem_bytes>>>(pQ, pK, pV, mask, pC);

    gemm_kernel<<<ggrid, 256>>>(pC, Wo, bo, pH, 0);
    ln_kernel<<<MTOT, 256>>>(pH, x, gam, bet, out);
}

// round 2
// speedup vs baseline: 1.7029x; 1.7029x over previous
#include <cuda_runtime.h>
#include <cstdint>

#define BATCH 4
#define SEQ   2048
#define DMODEL 1024
#define NHEAD 16
#define DHEAD 64
#define MTOT  (BATCH*SEQ)   // 8192

// ---------------- scratch (static device globals; no runtime alloc) ----------
__device__ float g_Q[BATCH*NHEAD*SEQ*DHEAD];   // 32 MB, [B,H,S,DH]
__device__ float g_K[BATCH*NHEAD*SEQ*DHEAD];
__device__ float g_V[BATCH*NHEAD*SEQ*DHEAD];
__device__ float g_ctx[MTOT*DMODEL];           // [B*S, D]
__device__ float g_h[MTOT*DMODEL];             // O-proj output

// ---------------- helpers ----------------------------------------------------
__device__ __forceinline__ float to_tf32(float x) {
    asm("cvt.rna.tf32.f32 %0, %0;" : "+f"(x));
    return x;
}

__device__ __forceinline__ void mma_tf32(float c[4], const uint32_t a[4], const uint32_t b[2]) {
    asm volatile(
        "mma.sync.aligned.m16n8k8.row.col.f32.tf32.tf32.f32 "
        "{%0,%1,%2,%3}, {%4,%5,%6,%7}, {%8,%9}, {%0,%1,%2,%3};"
        : "+f"(c[0]), "+f"(c[1]), "+f"(c[2]), "+f"(c[3])
        : "r"(a[0]), "r"(a[1]), "r"(a[2]), "r"(a[3]), "r"(b[0]), "r"(b[1]));
}

// ---------------- GEMM: out = A[M,K] @ W[K,N] + bias --------------------------
// BM=128, BN=128, BK=32. 256 threads = 8 warps in a 4(m) x 2(n) grid.
// Warp tile 32x64 = 2 m-frags (16) x 8 n-frags (8). tf32 mma, fp32 accum.
#define BM 128
#define BN 128
#define BK 32
#define LDB 136   // B smem stride: 136%32=8 -> conflict-free b-frag reads

__global__ __launch_bounds__(256) void gemm_kernel(
    const float* __restrict__ A, const float* __restrict__ W,
    const float* __restrict__ bias, float* __restrict__ out, int split_heads)
{
    __shared__ float Asm[BM][BK + 4];   // stride 36
    __shared__ float Bsm[BK][LDB];

    const int tid  = threadIdx.x;
    const int lane = tid & 31;
    const int warp = tid >> 5;
    const int wm   = warp >> 1;         // 0..3
    const int wn   = warp & 1;          // 0..1
    const int m0   = blockIdx.y * BM;
    const int n0   = blockIdx.x * BN;

    float acc[2][8][4];
#pragma unroll
    for (int im = 0; im < 2; im++)
#pragma unroll
        for (int in = 0; in < 8; in++)
#pragma unroll
            for (int k = 0; k < 4; k++) acc[im][in][k] = 0.f;

    for (int k0 = 0; k0 < DMODEL; k0 += BK) {
        // A tile 128x32: 1024 float4 / 256 thr = 4 each
#pragma unroll
        for (int i = 0; i < 4; i++) {
            int idx = tid + i * 256;
            int r = idx >> 3, c4 = (idx & 7) * 4;
            float4 v = *(const float4*)(A + (size_t)(m0 + r) * DMODEL + k0 + c4);
            Asm[r][c4 + 0] = to_tf32(v.x);
            Asm[r][c4 + 1] = to_tf32(v.y);
            Asm[r][c4 + 2] = to_tf32(v.z);
            Asm[r][c4 + 3] = to_tf32(v.w);
        }
        // B tile 32x128: 1024 float4 / 256 thr = 4 each
#pragma unroll
        for (int i = 0; i < 4; i++) {
            int idx = tid + i * 256;
            int r = idx >> 5, c4 = (idx & 31) * 4;
            float4 v = *(const float4*)(W + (size_t)(k0 + r) * DMODEL + n0 + c4);
            Bsm[r][c4 + 0] = to_tf32(v.x);
            Bsm[r][c4 + 1] = to_tf32(v.y);
            Bsm[r][c4 + 2] = to_tf32(v.z);
            Bsm[r][c4 + 3] = to_tf32(v.w);
        }
        __syncthreads();

#pragma unroll
        for (int ks = 0; ks < BK / 8; ks++) {
            const int ck = ks * 8 + (lane & 3);
            uint32_t afr[2][4];
#pragma unroll
            for (int im = 0; im < 2; im++) {
                int r = wm * 32 + im * 16 + (lane >> 2);
                afr[im][0] = __float_as_uint(Asm[r][ck]);
                afr[im][1] = __float_as_uint(Asm[r + 8][ck]);
                afr[im][2] = __float_as_uint(Asm[r][ck + 4]);
                afr[im][3] = __float_as_uint(Asm[r + 8][ck + 4]);
            }
            uint32_t bfr[8][2];
#pragma unroll
            for (int in = 0; in < 8; in++) {
                int c = wn * 64 + in * 8 + (lane >> 2);
                bfr[in][0] = __float_as_uint(Bsm[ks * 8 + (lane & 3)][c]);
                bfr[in][1] = __float_as_uint(Bsm[ks * 8 + (lane & 3) + 4][c]);
            }
#pragma unroll
            for (int im = 0; im < 2; im++)
#pragma unroll
                for (int in = 0; in < 8; in++)
                    mma_tf32(acc[im][in], afr[im], bfr[in]);
        }
        __syncthreads();
    }

    // epilogue: + bias, store (optionally head-split to [B,H,S,DH])
#pragma unroll
    for (int im = 0; im < 2; im++) {
#pragma unroll
        for (int in = 0; in < 8; in++) {
            int r = m0 + wm * 32 + im * 16 + (lane >> 2);
            int c = n0 + wn * 64 + in * 8 + 2 * (lane & 3);
            float b0 = bias[c], b1 = bias[c + 1];
            float2 v0 = make_float2(acc[im][in][0] + b0, acc[im][in][1] + b1);
            float2 v1 = make_float2(acc[im][in][2] + b0, acc[im][in][3] + b1);
            if (split_heads) {
                int b = r >> 11, s = r & (SEQ - 1);
                int h = c >> 6,  d = c & (DHEAD - 1);
                size_t base = (((size_t)(b * NHEAD + h) * SEQ + s) * DHEAD + d);
                *(float2*)(out + base) = v0;
                *(float2*)(out + base + 8 * DHEAD) = v1;
            } else {
                size_t base = (size_t)r * DMODEL + c;
                *(float2*)(out + base) = v0;
                *(float2*)(out + base + (size_t)8 * DMODEL) = v1;
            }
        }
    }
}

// ---------------- flash attention (FA2-style, register softmax) --------------
// One CTA: (b, h, 128-query tile). 256 threads = 8 warps; warp w owns query
// rows [w*16, w*16+16) across the FULL 64-key tile width. S stays in regs;
// softmax = register reduce + 2 shfl. P goes through a per-warp smem strip
// (producer==consumer -> __syncwarp only). 1 block barrier per key tile.
#define AQ   128   // queries per CTA
#define LDK  68    // K smem stride (conflict-free for 4n+k pattern)
#define LDV  72    // V smem stride: 72%32=8 -> conflict-free for 8k+n pattern
#define LDP  68    // P / Q-staging stride

__global__ __launch_bounds__(256) void attn_kernel(
    const float* __restrict__ Q, const float* __restrict__ K,
    const float* __restrict__ V, const float* __restrict__ mask,
    float* __restrict__ ctx)
{
    extern __shared__ float sm[];
    float* Ks  = sm;                       // [64][LDK]
    float* Vs  = Ks + 64 * LDK;            // [64][LDV]
    float* Ps  = Vs + 64 * LDV;            // [128][LDP] (also Q staging)
    float* msk = Ps + AQ * LDP;            // [64]

    const int tid  = threadIdx.x;
    const int lane = tid & 31;
    const int warp = tid >> 5;

    const int q0 = blockIdx.x * AQ;
    const int h  = blockIdx.y;
    const int b  = blockIdx.z;

    const float* Qp = Q + (((size_t)(b * NHEAD + h) * SEQ + q0) * DHEAD);
    const float* Kp = K + ((size_t)(b * NHEAD + h) * SEQ) * DHEAD;
    const float* Vp = V + ((size_t)(b * NHEAD + h) * SEQ) * DHEAD;

    // ---- stage Q (scaled by 1/8, tf32) through Ps, then pull into registers
#pragma unroll
    for (int i = 0; i < 8; i++) {
        int idx = tid + i * 256;               // 128 rows x 16 float4
        int r = idx >> 4, c4 = (idx & 15) * 4;
        float4 v = *(const float4*)(Qp + (size_t)r * DHEAD + c4);
        Ps[r * LDP + c4 + 0] = to_tf32(v.x * 0.125f);
        Ps[r * LDP + c4 + 1] = to_tf32(v.y * 0.125f);
        Ps[r * LDP + c4 + 2] = to_tf32(v.z * 0.125f);
        Ps[r * LDP + c4 + 3] = to_tf32(v.w * 0.125f);
    }
    __syncthreads();

    uint32_t qf[8][4];
    {
        const int r = warp * 16 + (lane >> 2);
#pragma unroll
        for (int ks = 0; ks < 8; ks++) {
            const int ck = ks * 8 + (lane & 3);
            qf[ks][0] = __float_as_uint(Ps[r * LDP + ck]);
            qf[ks][1] = __float_as_uint(Ps[(r + 8) * LDP + ck]);
            qf[ks][2] = __float_as_uint(Ps[r * LDP + ck + 4]);
            qf[ks][3] = __float_as_uint(Ps[(r + 8) * LDP + ck + 4]);
        }
    }
    __syncthreads();   // Ps now free for P

    float m0 = -1e30f, m1 = -1e30f, l0 = 0.f, l1 = 0.f;
    float oacc[8][4];
#pragma unroll
    for (int in = 0; in < 8; in++)
#pragma unroll
        for (int k = 0; k < 4; k++) oacc[in][k] = 0.f;

    for (int kt = 0; kt < SEQ / 64; kt++) {
        const int key0 = kt * 64;
        // ---- coop load K,V (tf32) + mask slice
#pragma unroll
        for (int i = 0; i < 4; i++) {
            int idx = tid + i * 256;               // 64 rows x 16 float4
            int r = idx >> 4, c4 = (idx & 15) * 4;
            float4 kv = *(const float4*)(Kp + (size_t)(key0 + r) * DHEAD + c4);
            Ks[r * LDK + c4 + 0] = to_tf32(kv.x);
            Ks[r * LDK + c4 + 1] = to_tf32(kv.y);
            Ks[r * LDK + c4 + 2] = to_tf32(kv.z);
            Ks[r * LDK + c4 + 3] = to_tf32(kv.w);
            float4 vv = *(const float4*)(Vp + (size_t)(key0 + r) * DHEAD + c4);
            Vs[r * LDV + c4 + 0] = to_tf32(vv.x);
            Vs[r * LDV + c4 + 1] = to_tf32(vv.y);
            Vs[r * LDV + c4 + 2] = to_tf32(vv.z);
            Vs[r * LDV + c4 + 3] = to_tf32(vv.w);
        }
        if (tid < 64) msk[tid] = mask[(size_t)b * SEQ + key0 + tid];
        __syncthreads();

        // ---- S = Q @ K^T  (warp: 16 x 64, all in registers)
        float sacc[8][4];
#pragma unroll
        for (int in = 0; in < 8; in++)
#pragma unroll
            for (int k = 0; k < 4; k++) sacc[in][k] = 0.f;

#pragma unroll
        for (int ks = 0; ks < 8; ks++) {
            const int ck = ks * 8 + (lane & 3);
#pragma unroll
            for (int in = 0; in < 8; in++) {
                int n = in * 8 + (lane >> 2);
                uint32_t bf[2] = {
                    __float_as_uint(Ks[n * LDK + ck]),
                    __float_as_uint(Ks[n * LDK + ck + 4]) };
                mma_tf32(sacc[in], qf[ks], bf);
            }
        }

        // ---- mask + register online softmax
        float mx0 = -1e30f, mx1 = -1e30f;
#pragma unroll
        for (int in = 0; in < 8; in++) {
            int c = in * 8 + 2 * (lane & 3);
            float mv0 = msk[c], mv1 = msk[c + 1];
            sacc[in][0] += mv0; sacc[in][1] += mv1;
            sacc[in][2] += mv0; sacc[in][3] += mv1;
            mx0 = fmaxf(mx0, fmaxf(sacc[in][0], sacc[in][1]));
            mx1 = fmaxf(mx1, fmaxf(sacc[in][2], sacc[in][3]));
        }
        mx0 = fmaxf(mx0, __shfl_xor_sync(0xffffffffu, mx0, 1));
        mx0 = fmaxf(mx0, __shfl_xor_sync(0xffffffffu, mx0, 2));
        mx1 = fmaxf(mx1, __shfl_xor_sync(0xffffffffu, mx1, 1));
        mx1 = fmaxf(mx1, __shfl_xor_sync(0xffffffffu, mx1, 2));

        const float mn0 = fmaxf(m0, mx0), mn1 = fmaxf(m1, mx1);
        const float a0 = __expf(m0 - mn0), a1 = __expf(m1 - mn1);
        m0 = mn0; m1 = mn1;

        const int rp = warp * 16 + (lane >> 2);
        float rs0 = 0.f, rs1 = 0.f;
#pragma unroll
        for (int in = 0; in < 8; in++) {
            int c = in * 8 + 2 * (lane & 3);
            float p0 = __expf(sacc[in][0] - mn0);
            float p1 = __expf(sacc[in][1] - mn0);
            float p2 = __expf(sacc[in][2] - mn1);
            float p3 = __expf(sacc[in][3] - mn1);
            rs0 += p0 + p1; rs1 += p2 + p3;
            *(float2*)(Ps + rp * LDP + c)       = make_float2(to_tf32(p0), to_tf32(p1));
            *(float2*)(Ps + (rp + 8) * LDP + c) = make_float2(to_tf32(p2), to_tf32(p3));
        }
        rs0 += __shfl_xor_sync(0xffffffffu, rs0, 1);
        rs0 += __shfl_xor_sync(0xffffffffu, rs0, 2);
        rs1 += __shfl_xor_sync(0xffffffffu, rs1, 1);
        rs1 += __shfl_xor_sync(0xffffffffu, rs1, 2);
        l0 = l0 * a0 + rs0;
        l1 = l1 * a1 + rs1;

#pragma unroll
        for (int in = 0; in < 8; in++) {
            oacc[in][0] *= a0; oacc[in][1] *= a0;
            oacc[in][2] *= a1; oacc[in][3] *= a1;
        }
        __syncwarp();   // P strip: producer == consumer warp

        // ---- O += P @ V
#pragma unroll
        for (int ks = 0; ks < 8; ks++) {
            const int ck = ks * 8 + (lane & 3);
            uint32_t af[4] = {
                __float_as_uint(Ps[rp * LDP + ck]),
                __float_as_uint(Ps[(rp + 8) * LDP + ck]),
                __float_as_uint(Ps[rp * LDP + ck + 4]),
                __float_as_uint(Ps[(rp + 8) * LDP + ck + 4]) };
#pragma unroll
            for (int in = 0; in < 8; in++) {
                int n = in * 8 + (lane >> 2);
                uint32_t bf[2] = {
                    __float_as_uint(Vs[ck * LDV + n]),
                    __float_as_uint(Vs[(ck + 4) * LDV + n]) };
                mma_tf32(oacc[in], af, bf);
            }
        }
        __syncthreads();   // before next tile overwrites Ks/Vs
    }

    // ---- finalize: /l, write ctx [B,S,D]  (d = h*64 + col)
    {
        const int rp = warp * 16 + (lane >> 2);
        const float il0 = 1.f / l0, il1 = 1.f / l1;
#pragma unroll
        for (int in = 0; in < 8; in++) {
            int c = in * 8 + 2 * (lane & 3);
            size_t base = ((size_t)b * SEQ + q0 + rp) * DMODEL + h * DHEAD + c;
            *(float2*)(ctx + base) = make_float2(oacc[in][0] * il0, oacc[in][1] * il0);
            *(float2*)(ctx + base + (size_t)8 * DMODEL) =
                make_float2(oacc[in][2] * il1, oacc[in][3] * il1);
        }
    }
}

// ---------------- residual + LayerNorm ---------------------------------------
__global__ __launch_bounds__(256) void ln_kernel(
    const float* __restrict__ hbuf, const float* __restrict__ x,
    const float* __restrict__ gamma, const float* __restrict__ beta,
    float* __restrict__ out)
{
    const int row = blockIdx.x;
    const int tid = threadIdx.x;
    const int lane = tid & 31, warp = tid >> 5;

    const float4* hp = (const float4*)(hbuf + (size_t)row * DMODEL);
    const float4* xp = (const float4*)(x + (size_t)row * DMODEL);
    float4 hv = hp[tid], xv = xp[tid];
    float4 y = make_float4(hv.x + xv.x, hv.y + xv.y, hv.z + xv.z, hv.w + xv.w);

    float s  = y.x + y.y + y.z + y.w;
    float sq = y.x * y.x + y.y * y.y + y.z * y.z + y.w * y.w;
#pragma unroll
    for (int o = 16; o; o >>= 1) {
        s  += __shfl_xor_sync(0xffffffffu, s, o);
        sq += __shfl_xor_sync(0xffffffffu, sq, o);
    }
    __shared__ float ss[8], ssq[8];
    if (lane == 0) { ss[warp] = s; ssq[warp] = sq; }
    __syncthreads();
    if (warp == 0) {
        s  = (lane < 8) ? ss[lane]  : 0.f;
        sq = (lane < 8) ? ssq[lane] : 0.f;
#pragma unroll
        for (int o = 4; o; o >>= 1) {
            s  += __shfl_xor_sync(0xffffffffu, s, o);
            sq += __shfl_xor_sync(0xffffffffu, sq, o);
        }
        if (lane == 0) { ss[0] = s; ssq[0] = sq; }
    }
    __syncthreads();
    s = ss[0]; sq = ssq[0];

    const float mu   = s * (1.f / DMODEL);
    const float var  = sq * (1.f / DMODEL) - mu * mu;
    const float rstd = rsqrtf(var + 1e-12f);

    float4 g = ((const float4*)gamma)[tid];
    float4 bt = ((const float4*)beta)[tid];
    float4 o;
    o.x = (y.x - mu) * rstd * g.x + bt.x;
    o.y = (y.y - mu) * rstd * g.y + bt.y;
    o.z = (y.z - mu) * rstd * g.z + bt.z;
    o.w = (y.w - mu) * rstd * g.w + bt.w;
    ((float4*)(out + (size_t)row * DMODEL))[tid] = o;
}

// ---------------- launch ------------------------------------------------------
extern "C" void kernel_launch(void* const* d_in, const int* in_sizes, int n_in,
                              void* d_out, int out_size)
{
    const float* x    = (const float*)d_in[0];
    const float* mask = (const float*)d_in[1];
    const float* Wq   = (const float*)d_in[2];
    const float* bq   = (const float*)d_in[3];
    const float* Wk   = (const float*)d_in[4];
    const float* bk   = (const float*)d_in[5];
    const float* Wv   = (const float*)d_in[6];
    const float* bv   = (const float*)d_in[7];
    const float* Wo   = (const float*)d_in[8];
    const float* bo   = (const float*)d_in[9];
    const float* gam  = (const float*)d_in[10];
    const float* bet  = (const float*)d_in[11];
    float* out = (float*)d_out;

    float *pQ, *pK, *pV, *pC, *pH;
    cudaGetSymbolAddress((void**)&pQ, g_Q);
    cudaGetSymbolAddress((void**)&pK, g_K);
    cudaGetSymbolAddress((void**)&pV, g_V);
    cudaGetSymbolAddress((void**)&pC, g_ctx);
    cudaGetSymbolAddress((void**)&pH, g_h);

    dim3 ggrid(DMODEL / BN, MTOT / BM);   // (8, 64)
    gemm_kernel<<<ggrid, 256>>>(x, Wq, bq, pQ, 1);
    gemm_kernel<<<ggrid, 256>>>(x, Wk, bk, pK, 1);
    gemm_kernel<<<ggrid, 256>>>(x, Wv, bv, pV, 1);

    const int smem_bytes = (64 * LDK + 64 * LDV + AQ * LDP + 64) * (int)sizeof(float);
    cudaFuncSetAttribute(attn_kernel, cudaFuncAttributeMaxDynamicSharedMemorySize, smem_bytes);
    attn_kernel<<<dim3(SEQ / AQ, NHEAD, BATCH), 256, smem_bytes>>>(pQ, pK, pV, mask, pC);

    gemm_kernel<<<ggrid, 256>>>(pC, Wo, bo, pH, 0);
    ln_kernel<<<MTOT, 256>>>(pH, x, gam, bet, out);
}

// round 6
// speedup vs baseline: 3.5748x; 2.0993x over previous
#include <cuda_runtime.h>
#include <cuda_bf16.h>
#include <cstdint>

#define BATCH 4
#define SEQ   2048
#define DMODEL 1024
#define NHEAD 16
#define DHEAD 64
#define MTOT  (BATCH*SEQ)   // 8192

// ---------------- scratch (static device globals; no runtime alloc) ----------
__device__ __nv_bfloat16 g_xb [MTOT*DMODEL];            // x in bf16
__device__ __nv_bfloat16 g_Qb [BATCH*NHEAD*SEQ*DHEAD];  // [B,H,S,DH] bf16
__device__ __nv_bfloat16 g_Kb [BATCH*NHEAD*SEQ*DHEAD];
__device__ __nv_bfloat16 g_Vb [BATCH*NHEAD*SEQ*DHEAD];
__device__ __nv_bfloat16 g_ctxb[MTOT*DMODEL];           // attention out, bf16
__device__ __nv_bfloat16 g_Wtb[4*DMODEL*DMODEL];        // transposed bf16 weights
__device__ float         g_h  [MTOT*DMODEL];            // O-proj out, fp32

// ---------------- low-level helpers ------------------------------------------
__device__ __forceinline__ uint32_t smem_u32(const void* p) {
    uint32_t a;
    asm("{ .reg .u64 t; cvta.to.shared.u64 t, %1; cvt.u32.u64 %0, t; }" : "=r"(a) : "l"(p));
    return a;
}
__device__ __forceinline__ void cpasync16(uint32_t dst, const void* src) {
    asm volatile("cp.async.cg.shared.global [%0], [%1], 16;" :: "r"(dst), "l"(src));
}
__device__ __forceinline__ void cp_commit() { asm volatile("cp.async.commit_group;"); }
__device__ __forceinline__ void cp_wait0()  { asm volatile("cp.async.wait_group 0;"); }

__device__ __forceinline__ void mma_bf16(float c[4], const uint32_t a[4],
                                         uint32_t b0, uint32_t b1) {
    asm volatile(
        "mma.sync.aligned.m16n8k16.row.col.f32.bf16.bf16.f32 "
        "{%0,%1,%2,%3}, {%4,%5,%6,%7}, {%8,%9}, {%0,%1,%2,%3};"
        : "+f"(c[0]), "+f"(c[1]), "+f"(c[2]), "+f"(c[3])
        : "r"(a[0]), "r"(a[1]), "r"(a[2]), "r"(a[3]), "r"(b0), "r"(b1));
}
__device__ __forceinline__ void ldsm_x4_t(uint32_t& r0, uint32_t& r1,
                                          uint32_t& r2, uint32_t& r3, uint32_t addr) {
    asm volatile("ldmatrix.sync.aligned.m8n8.x4.trans.shared.b16 {%0,%1,%2,%3}, [%4];"
        : "=r"(r0), "=r"(r1), "=r"(r2), "=r"(r3) : "r"(addr));
}
__device__ __forceinline__ uint32_t pack_bf16(float lo, float hi) {
    __nv_bfloat162 t = __float22bfloat162_rn(make_float2(lo, hi));  // .x=lo, .y=hi
    return *reinterpret_cast<uint32_t*>(&t);
}

// ---------------- fp32 -> bf16 convert ----------------------------------------
__global__ __launch_bounds__(256) void cvt_kernel(
    const float* __restrict__ x, __nv_bfloat162* __restrict__ o)
{
    size_t i = (size_t)blockIdx.x * 256 + threadIdx.x;   // over float4 (2M)
    float4 v = ((const float4*)x)[i];
    o[2 * i]     = __float22bfloat162_rn(make_float2(v.x, v.y));
    o[2 * i + 1] = __float22bfloat162_rn(make_float2(v.z, v.w));
}

// ---------------- transpose + convert: W[K][N] fp32 -> Wt[N][K] bf16 ----------
__global__ __launch_bounds__(256) void tr_kernel(
    const float* __restrict__ src, __nv_bfloat16* __restrict__ dst)
{
    __shared__ float t[32][33];
    int x = blockIdx.x * 32 + threadIdx.x;
    int y = blockIdx.y * 32 + threadIdx.y;
#pragma unroll
    for (int j = 0; j < 32; j += 8)
        t[threadIdx.y + j][threadIdx.x] = src[(size_t)(y + j) * DMODEL + x];
    __syncthreads();
    int x2 = blockIdx.y * 32 + threadIdx.x;
    int y2 = blockIdx.x * 32 + threadIdx.y;
#pragma unroll
    for (int j = 0; j < 32; j += 8)
        dst[(size_t)(y2 + j) * DMODEL + x2] = __float2bfloat16(t[threadIdx.x][threadIdx.y + j]);
}

// ---------------- bf16 GEMM: out = A[M,1024] @ Wt^T + bias --------------------
// A, Wt bf16 K-major. BM=BN=128, BK=32. 8 warps (4m x 2n), warp tile 32x64.
// mma m16n8k16, fp32 acc. cp.async 2-stage. Row pad: 20 words (80B) -> the
// (lane>>2, lane&3) fragment pattern hits distinct bank quads (20r+c mod 32).
#define GBM 128
#define GBN 128
#define GBK 32
#define GLD 20                 // words per smem row (16 data + 4 pad)
#define GSTG (128*GLD)         // 2560 words per stage

__global__ __launch_bounds__(256, 2) void gemm_bf16(
    const __nv_bfloat16* __restrict__ A, const __nv_bfloat16* __restrict__ Bt,
    const float* __restrict__ bias, void* __restrict__ outp,
    int split_heads, float oscale)
{
    __shared__ __align__(16) uint32_t gsm[4 * GSTG];   // A0,A1,B0,B1 = 40KB
    const uint32_t sb = smem_u32(gsm);

    const int tid  = threadIdx.x;
    const int lane = tid & 31;
    const int warp = tid >> 5;
    const int wm   = warp >> 1;          // 0..3
    const int wn   = warp & 1;           // 0..1
    const int m0   = blockIdx.y * GBM;
    const int n0   = blockIdx.x * GBN;

    const __nv_bfloat16* Abase = A  + (size_t)m0 * DMODEL;
    const __nv_bfloat16* Bbase = Bt + (size_t)n0 * DMODEL;

    float acc[2][8][4];
#pragma unroll
    for (int im = 0; im < 2; im++)
#pragma unroll
        for (int in = 0; in < 8; in++)
#pragma unroll
            for (int k = 0; k < 4; k++) acc[im][in][k] = 0.f;

#define GLOAD(c, s) do {                                                       \
        _Pragma("unroll")                                                      \
        for (int i_ = 0; i_ < 2; i_++) {                                       \
            int idx_ = tid + i_ * 256;            /* 0..511: A rows */         \
            int r_ = idx_ >> 2, q_ = idx_ & 3;                                 \
            cpasync16(sb + ((s) * GSTG + r_ * GLD + q_ * 4) * 4,               \
                      Abase + (size_t)r_ * DMODEL + (c) * GBK + q_ * 8);       \
        }                                                                      \
        _Pragma("unroll")                                                      \
        for (int i_ = 0; i_ < 2; i_++) {                                       \
            int idx_ = tid + i_ * 256;            /* B rows */                 \
            int r_ = idx_ >> 2, q_ = idx_ & 3;                                 \
            cpasync16(sb + ((2 + (s)) * GSTG + r_ * GLD + q_ * 4) * 4,         \
                      Bbase + (size_t)r_ * DMODEL + (c) * GBK + q_ * 8);       \
        }                                                                      \
        cp_commit();                                                           \
    } while (0)

    GLOAD(0, 0);
    const int NCH = DMODEL / GBK;   // 32
    for (int c = 0; c < NCH; c++) {
        const int bsl = c & 1;
        cp_wait0();
        __syncthreads();
        if (c + 1 < NCH) GLOAD(c + 1, 1 - bsl);

        const uint32_t* As = gsm + bsl * GSTG;
        const uint32_t* Bs = gsm + (2 + bsl) * GSTG;

#pragma unroll
        for (int ks = 0; ks < 2; ks++) {
            const int kw = ks * 8 + (lane & 3);
            uint32_t a[2][4];
#pragma unroll
            for (int im = 0; im < 2; im++) {
                int base = (wm * 32 + im * 16 + (lane >> 2)) * GLD + kw;
                a[im][0] = As[base];
                a[im][1] = As[base + 8 * GLD];
                a[im][2] = As[base + 4];
                a[im][3] = As[base + 8 * GLD + 4];
            }
#pragma unroll
            for (int in = 0; in < 8; in++) {
                int rb = (wn * 64 + in * 8 + (lane >> 2)) * GLD + kw;
                uint32_t b0 = Bs[rb], b1 = Bs[rb + 4];
                mma_bf16(acc[0][in], a[0], b0, b1);
                mma_bf16(acc[1][in], a[1], b0, b1);
            }
        }
        __syncthreads();
    }

    // epilogue
#pragma unroll
    for (int im = 0; im < 2; im++) {
#pragma unroll
        for (int in = 0; in < 8; in++) {
            int row = m0 + wm * 32 + im * 16 + (lane >> 2);
            int col = n0 + wn * 64 + in * 8 + 2 * (lane & 3);
            float b0 = bias[col], b1 = bias[col + 1];
            float v00 = (acc[im][in][0] + b0) * oscale;
            float v01 = (acc[im][in][1] + b1) * oscale;
            float v10 = (acc[im][in][2] + b0) * oscale;
            float v11 = (acc[im][in][3] + b1) * oscale;
            if (split_heads) {
                __nv_bfloat16* ob = (__nv_bfloat16*)outp;
                int bb = row >> 11, s = row & (SEQ - 1);
                int hh = col >> 6,  d = col & 63;
                size_t base = (((size_t)(bb * NHEAD + hh) * SEQ + s) * DHEAD + d);
                *(uint32_t*)(ob + base)              = pack_bf16(v00, v01);
                *(uint32_t*)(ob + base + 8 * DHEAD)  = pack_bf16(v10, v11);
            } else {
                float* of = (float*)outp;
                size_t base = (size_t)row * DMODEL + col;
                *(float2*)(of + base)                       = make_float2(v00, v01);
                *(float2*)(of + base + (size_t)8 * DMODEL)  = make_float2(v10, v11);
            }
        }
    }
}

// ---------------- flash attention, bf16 mma, register-resident P --------------
// CTA: (b,h,128-query tile), 8 warps x 16 rows, full 64-key width per warp.
// K tile: scalar 32-bit LDS b-frags (row stride 144B -> conflict-free).
// V tile: ldmatrix.x4.trans. P: acc-frag == A-frag layout, packed in registers.
#define AQ 128
#define AROW 144                 // bytes per K/V smem row (128 data + 16 pad)
#define KOFF(s) ((s) * 9216)
#define VOFF(s) (18432 + (s) * 9216)
#define MOFF(s) (36864 + (s) * 256)
#define ASMEM 37376

__global__ __launch_bounds__(256, 2) void attn_kernel(
    const __nv_bfloat16* __restrict__ Q, const __nv_bfloat16* __restrict__ K,
    const __nv_bfloat16* __restrict__ V, const float* __restrict__ mask,
    __nv_bfloat16* __restrict__ ctx)
{
    __shared__ __align__(16) uint8_t smr[ASMEM];
    const uint32_t sb = smem_u32(smr);

    const int tid  = threadIdx.x;
    const int lane = tid & 31;
    const int warp = tid >> 5;

    const int q0 = blockIdx.x * AQ;
    const int h  = blockIdx.y;
    const int b  = blockIdx.z;

    const __nv_bfloat16* Qp = Q + (((size_t)(b * NHEAD + h) * SEQ + q0) * DHEAD);
    const __nv_bfloat16* Kp = K + ((size_t)(b * NHEAD + h) * SEQ) * DHEAD;
    const __nv_bfloat16* Vp = V + ((size_t)(b * NHEAD + h) * SEQ) * DHEAD;
    const float* Mp = mask + (size_t)b * SEQ;

#define APREFETCH(kt, s) do {                                                  \
        const int key0_ = (kt) * 64;                                           \
        _Pragma("unroll")                                                      \
        for (int i_ = 0; i_ < 2; i_++) {                                       \
            int idx_ = tid + i_ * 256;          /* 0..511 = 64 rows x 8 */     \
            int r_ = idx_ >> 3, q_ = idx_ & 7;                                 \
            cpasync16(sb + KOFF(s) + r_ * AROW + q_ * 16,                      \
                      Kp + (size_t)(key0_ + r_) * DHEAD + q_ * 8);             \
        }                                                                      \
        _Pragma("unroll")                                                      \
        for (int i_ = 0; i_ < 2; i_++) {                                       \
            int idx_ = tid + i_ * 256;                                         \
            int r_ = idx_ >> 3, q_ = idx_ & 7;                                 \
            cpasync16(sb + VOFF(s) + r_ * AROW + q_ * 16,                      \
                      Vp + (size_t)(key0_ + r_) * DHEAD + q_ * 8);             \
        }                                                                      \
        if (tid < 16)                                                          \
            cpasync16(sb + MOFF(s) + tid * 16, Mp + key0_ + tid * 4);          \
        cp_commit();                                                           \
    } while (0)

    APREFETCH(0, 0);

    // ---- Q fragments straight from gmem (bf16 pairs are mma-native)
    uint32_t qf[4][4];
    {
        const int r = q0 * 0 + warp * 16 + (lane >> 2);   // row within tile
#pragma unroll
        for (int ks = 0; ks < 4; ks++) {
            int k0 = ks * 16 + 2 * (lane & 3);
            qf[ks][0] = *(const uint32_t*)(Qp + (size_t)r * DHEAD + k0);
            qf[ks][1] = *(const uint32_t*)(Qp + (size_t)(r + 8) * DHEAD + k0);
            qf[ks][2] = *(const uint32_t*)(Qp + (size_t)r * DHEAD + k0 + 8);
            qf[ks][3] = *(const uint32_t*)(Qp + (size_t)(r + 8) * DHEAD + k0 + 8);
        }
    }

    float m0 = -1e30f, m1 = -1e30f, l0 = 0.f, l1 = 0.f;
    float oacc[8][4];
#pragma unroll
    for (int in = 0; in < 8; in++)
#pragma unroll
        for (int k = 0; k < 4; k++) oacc[in][k] = 0.f;

    // ldmatrix lane-offset (within a V stage): 4 matrices per x4 op
    const uint32_t vlaneoff =
        ((lane & 7) + ((lane & 8) ? 8u : 0u)) * AROW + ((lane & 16) ? 16u : 0u);

    for (int kt = 0; kt < SEQ / 64; kt++) {
        const int bsl = kt & 1;
        cp_wait0();
        __syncthreads();
        if (kt + 1 < SEQ / 64) APREFETCH(kt + 1, 1 - bsl);

        const uint32_t* Kw  = (const uint32_t*)(smr + KOFF(bsl));   // 36 words/row
        const float*    msk = (const float*)(smr + MOFF(bsl));
        const uint32_t  vbase = sb + VOFF(bsl);

        // ---- S = Q @ K^T  (16 x 64 per warp, registers)
        float sacc[8][4];
#pragma unroll
        for (int in = 0; in < 8; in++)
#pragma unroll
            for (int k = 0; k < 4; k++) sacc[in][k] = 0.f;

#pragma unroll
        for (int ks = 0; ks < 4; ks++) {
            const int kw = ks * 8 + (lane & 3);
#pragma unroll
            for (int in = 0; in < 8; in++) {
                int rb = (in * 8 + (lane >> 2)) * 36 + kw;
                mma_bf16(sacc[in], qf[ks], Kw[rb], Kw[rb + 4]);
            }
        }

        // ---- mask + register online softmax
        float mx0 = -1e30f, mx1 = -1e30f;
#pragma unroll
        for (int in = 0; in < 8; in++) {
            int c = in * 8 + 2 * (lane & 3);
            float mv0 = msk[c], mv1 = msk[c + 1];
            sacc[in][0] += mv0; sacc[in][1] += mv1;
            sacc[in][2] += mv0; sacc[in][3] += mv1;
            mx0 = fmaxf(mx0, fmaxf(sacc[in][0], sacc[in][1]));
            mx1 = fmaxf(mx1, fmaxf(sacc[in][2], sacc[in][3]));
        }
        mx0 = fmaxf(mx0, __shfl_xor_sync(0xffffffffu, mx0, 1));
        mx0 = fmaxf(mx0, __shfl_xor_sync(0xffffffffu, mx0, 2));
        mx1 = fmaxf(mx1, __shfl_xor_sync(0xffffffffu, mx1, 1));
        mx1 = fmaxf(mx1, __shfl_xor_sync(0xffffffffu, mx1, 2));

        const float mn0 = fmaxf(m0, mx0), mn1 = fmaxf(m1, mx1);
        const float a0 = __expf(m0 - mn0), a1 = __expf(m1 - mn1);
        m0 = mn0; m1 = mn1;

        uint32_t pk[8][2];
        float rs0 = 0.f, rs1 = 0.f;
#pragma unroll
        for (int in = 0; in < 8; in++) {
            float p0 = __expf(sacc[in][0] - mn0);
            float p1 = __expf(sacc[in][1] - mn0);
            float p2 = __expf(sacc[in][2] - mn1);
            float p3 = __expf(sacc[in][3] - mn1);
            rs0 += p0 + p1; rs1 += p2 + p3;
            pk[in][0] = pack_bf16(p0, p1);
            pk[in][1] = pack_bf16(p2, p3);
        }
        rs0 += __shfl_xor_sync(0xffffffffu, rs0, 1);
        rs0 += __shfl_xor_sync(0xffffffffu, rs0, 2);
        rs1 += __shfl_xor_sync(0xffffffffu, rs1, 1);
        rs1 += __shfl_xor_sync(0xffffffffu, rs1, 2);
        l0 = l0 * a0 + rs0;
        l1 = l1 * a1 + rs1;

#pragma unroll
        for (int in = 0; in < 8; in++) {
            oacc[in][0] *= a0; oacc[in][1] *= a0;
            oacc[in][2] *= a1; oacc[in][3] *= a1;
        }

        // ---- O += P @ V   (A-frags from pk registers; B via ldmatrix.trans)
#pragma unroll
        for (int ks = 0; ks < 4; ks++) {
            uint32_t a[4] = { pk[2 * ks][0], pk[2 * ks][1],
                              pk[2 * ks + 1][0], pk[2 * ks + 1][1] };
            uint32_t vk = vbase + (uint32_t)(ks * 16) * AROW + vlaneoff;
#pragma unroll
            for (int gi = 0; gi < 4; gi++) {
                uint32_t b0a, b1a, b0b, b1b;
                ldsm_x4_t(b0a, b1a, b0b, b1b, vk + gi * 32);
                mma_bf16(oacc[2 * gi],     a, b0a, b1a);
                mma_bf16(oacc[2 * gi + 1], a, b0b, b1b);
            }
        }
    }

    // ---- finalize: /l, write ctx bf16 [B,S,D]  (d = h*64 + col)
    {
        const int rp = warp * 16 + (lane >> 2);
        const float il0 = 1.f / l0, il1 = 1.f / l1;
#pragma unroll
        for (int in = 0; in < 8; in++) {
            int c = in * 8 + 2 * (lane & 3);
            size_t base = ((size_t)b * SEQ + q0 + rp) * DMODEL + h * DHEAD + c;
            *(uint32_t*)(ctx + base) =
                pack_bf16(oacc[in][0] * il0, oacc[in][1] * il0);
            *(uint32_t*)(ctx + base + (size_t)8 * DMODEL) =
                pack_bf16(oacc[in][2] * il1, oacc[in][3] * il1);
        }
    }
}

// ---------------- residual + LayerNorm ---------------------------------------
__global__ __launch_bounds__(256) void ln_kernel(
    const float* __restrict__ hbuf, const float* __restrict__ x,
    const float* __restrict__ gamma, const float* __restrict__ beta,
    float* __restrict__ out)
{
    const int row = blockIdx.x;
    const int tid = threadIdx.x;
    const int lane = tid & 31, warp = tid >> 5;

    const float4* hp = (const float4*)(hbuf + (size_t)row * DMODEL);
    const float4* xp = (const float4*)(x + (size_t)row * DMODEL);
    float4 hv = hp[tid], xv = xp[tid];
    float4 y = make_float4(hv.x + xv.x, hv.y + xv.y, hv.z + xv.z, hv.w + xv.w);

    float s  = y.x + y.y + y.z + y.w;
    float sq = y.x * y.x + y.y * y.y + y.z * y.z + y.w * y.w;
#pragma unroll
    for (int o = 16; o; o >>= 1) {
        s  += __shfl_xor_sync(0xffffffffu, s, o);
        sq += __shfl_xor_sync(0xffffffffu, sq, o);
    }
    __shared__ float ss[8], ssq[8];
    if (lane == 0) { ss[warp] = s; ssq[warp] = sq; }
    __syncthreads();
    if (warp == 0) {
        s  = (lane < 8) ? ss[lane]  : 0.f;
        sq = (lane < 8) ? ssq[lane] : 0.f;
#pragma unroll
        for (int o = 4; o; o >>= 1) {
            s  += __shfl_xor_sync(0xffffffffu, s, o);
            sq += __shfl_xor_sync(0xffffffffu, sq, o);
        }
        if (lane == 0) { ss[0] = s; ssq[0] = sq; }
    }
    __syncthreads();
    s = ss[0]; sq = ssq[0];

    const float mu   = s * (1.f / DMODEL);
    const float var  = sq * (1.f / DMODEL) - mu * mu;
    const float rstd = rsqrtf(var + 1e-12f);

    float4 g = ((const float4*)gamma)[tid];
    float4 bt = ((const float4*)beta)[tid];
    float4 o;
    o.x = (y.x - mu) * rstd * g.x + bt.x;
    o.y = (y.y - mu) * rstd * g.y + bt.y;
    o.z = (y.z - mu) * rstd * g.z + bt.z;
    o.w = (y.w - mu) * rstd * g.w + bt.w;
    ((float4*)(out + (size_t)row * DMODEL))[tid] = o;
}

// ---------------- launch ------------------------------------------------------
extern "C" void kernel_launch(void* const* d_in, const int* in_sizes, int n_in,
                              void* d_out, int out_size)
{
    const float* x    = (const float*)d_in[0];
    const float* mask = (const float*)d_in[1];
    const float* Wq   = (const float*)d_in[2];
    const float* bq   = (const float*)d_in[3];
    const float* Wk   = (const float*)d_in[4];
    const float* bk   = (const float*)d_in[5];
    const float* Wv   = (const float*)d_in[6];
    const float* bv   = (const float*)d_in[7];
    const float* Wo   = (const float*)d_in[8];
    const float* bo   = (const float*)d_in[9];
    const float* gam  = (const float*)d_in[10];
    const float* bet  = (const float*)d_in[11];
    float* out = (float*)d_out;

    __nv_bfloat16 *pxb, *pQ, *pK, *pV, *pC, *pWt;
    float *pH;
    cudaGetSymbolAddress((void**)&pxb, g_xb);
    cudaGetSymbolAddress((void**)&pQ,  g_Qb);
    cudaGetSymbolAddress((void**)&pK,  g_Kb);
    cudaGetSymbolAddress((void**)&pV,  g_Vb);
    cudaGetSymbolAddress((void**)&pC,  g_ctxb);
    cudaGetSymbolAddress((void**)&pWt, g_Wtb);
    cudaGetSymbolAddress((void**)&pH,  g_h);
    __nv_bfloat16* Wtq = pWt;
    __nv_bfloat16* Wtk = pWt + (size_t)DMODEL * DMODEL;
    __nv_bfloat16* Wtv = pWt + (size_t)2 * DMODEL * DMODEL;
    __nv_bfloat16* Wto = pWt + (size_t)3 * DMODEL * DMODEL;

    cvt_kernel<<<MTOT * DMODEL / 4 / 256, 256>>>(x, (__nv_bfloat162*)pxb);

    dim3 tgrid(32, 32), tblk(32, 8);
    tr_kernel<<<tgrid, tblk>>>(Wq, Wtq);
    tr_kernel<<<tgrid, tblk>>>(Wk, Wtk);
    tr_kernel<<<tgrid, tblk>>>(Wv, Wtv);
    tr_kernel<<<tgrid, tblk>>>(Wo, Wto);

    dim3 ggrid(DMODEL / GBN, MTOT / GBM);   // (8, 64)
    gemm_bf16<<<ggrid, 256>>>(pxb, Wtq, bq, pQ, 1, 0.125f);
    gemm_bf16<<<ggrid, 256>>>(pxb, Wtk, bk, pK, 1, 1.0f);
    gemm_bf16<<<ggrid, 256>>>(pxb, Wtv, bv, pV, 1, 1.0f);

    attn_kernel<<<dim3(SEQ / AQ, NHEAD, BATCH), 256>>>(pQ, pK, pV, mask, pC);

    gemm_bf16<<<ggrid, 256>>>(pC, Wto, bo, pH, 0, 1.0f);
    ln_kernel<<<MTOT, 256>>>(pH, x, gam, bet, out);
}

// round 7
// speedup vs baseline: 3.8831x; 1.0863x over previous
#include <cuda_runtime.h>
#include <cuda_bf16.h>
#include <cstdint>

#define BATCH 4
#define SEQ   2048
#define DMODEL 1024
#define NHEAD 16
#define DHEAD 64
#define MTOT  (BATCH*SEQ)   // 8192

// ---------------- scratch (static device globals; no runtime alloc) ----------
__device__ __nv_bfloat16 g_xb [MTOT*DMODEL];            // x in bf16
__device__ __nv_bfloat16 g_Qb [BATCH*NHEAD*SEQ*DHEAD];  // [B,H,S,DH] bf16
__device__ __nv_bfloat16 g_Kb [BATCH*NHEAD*SEQ*DHEAD];
__device__ __nv_bfloat16 g_Vb [BATCH*NHEAD*SEQ*DHEAD];
__device__ __nv_bfloat16 g_ctxb[MTOT*DMODEL];           // attention out, bf16
__device__ __nv_bfloat16 g_Wtb[4*DMODEL*DMODEL];        // transposed bf16 weights
__device__ float         g_h  [MTOT*DMODEL];            // O-proj out, fp32

// ---------------- low-level helpers ------------------------------------------
__device__ __forceinline__ uint32_t smem_u32(const void* p) {
    uint32_t a;
    asm("{ .reg .u64 t; cvta.to.shared.u64 t, %1; cvt.u32.u64 %0, t; }" : "=r"(a) : "l"(p));
    return a;
}
__device__ __forceinline__ void cpasync16(uint32_t dst, const void* src) {
    asm volatile("cp.async.cg.shared.global [%0], [%1], 16;" :: "r"(dst), "l"(src));
}
__device__ __forceinline__ void cp_commit() { asm volatile("cp.async.commit_group;"); }
__device__ __forceinline__ void cp_wait0()  { asm volatile("cp.async.wait_group 0;"); }

__device__ __forceinline__ void mma_bf16(float c[4], const uint32_t a[4],
                                         uint32_t b0, uint32_t b1) {
    asm volatile(
        "mma.sync.aligned.m16n8k16.row.col.f32.bf16.bf16.f32 "
        "{%0,%1,%2,%3}, {%4,%5,%6,%7}, {%8,%9}, {%0,%1,%2,%3};"
        : "+f"(c[0]), "+f"(c[1]), "+f"(c[2]), "+f"(c[3])
        : "r"(a[0]), "r"(a[1]), "r"(a[2]), "r"(a[3]), "r"(b0), "r"(b1));
}
__device__ __forceinline__ void ldsm_x4(uint32_t& r0, uint32_t& r1,
                                        uint32_t& r2, uint32_t& r3, uint32_t addr) {
    asm volatile("ldmatrix.sync.aligned.m8n8.x4.shared.b16 {%0,%1,%2,%3}, [%4];"
        : "=r"(r0), "=r"(r1), "=r"(r2), "=r"(r3) : "r"(addr));
}
__device__ __forceinline__ void ldsm_x4_t(uint32_t& r0, uint32_t& r1,
                                          uint32_t& r2, uint32_t& r3, uint32_t addr) {
    asm volatile("ldmatrix.sync.aligned.m8n8.x4.trans.shared.b16 {%0,%1,%2,%3}, [%4];"
        : "=r"(r0), "=r"(r1), "=r"(r2), "=r"(r3) : "r"(addr));
}
__device__ __forceinline__ uint32_t pack_bf16(float lo, float hi) {
    __nv_bfloat162 t = __float22bfloat162_rn(make_float2(lo, hi));
    return *reinterpret_cast<uint32_t*>(&t);
}

// ---------------- fp32 -> bf16 convert ----------------------------------------
__global__ __launch_bounds__(256) void cvt_kernel(
    const float* __restrict__ x, __nv_bfloat162* __restrict__ o)
{
    size_t i = (size_t)blockIdx.x * 256 + threadIdx.x;   // over float4
    float4 v = ((const float4*)x)[i];
    o[2 * i]     = __float22bfloat162_rn(make_float2(v.x, v.y));
    o[2 * i + 1] = __float22bfloat162_rn(make_float2(v.z, v.w));
}

// -------- transpose + convert all 4 weights: W[K][N] fp32 -> Wt[N][K] bf16 ----
__global__ __launch_bounds__(256) void tr_kernel(
    const float* __restrict__ s0, const float* __restrict__ s1,
    const float* __restrict__ s2, const float* __restrict__ s3,
    __nv_bfloat16* __restrict__ dstb)
{
    const float* src = (blockIdx.z == 0) ? s0 : (blockIdx.z == 1) ? s1
                     : (blockIdx.z == 2) ? s2 : s3;
    __nv_bfloat16* dst = dstb + (size_t)blockIdx.z * DMODEL * DMODEL;
    __shared__ float t[32][33];
    int x = blockIdx.x * 32 + threadIdx.x;
    int y = blockIdx.y * 32 + threadIdx.y;
#pragma unroll
    for (int j = 0; j < 32; j += 8)
        t[threadIdx.y + j][threadIdx.x] = src[(size_t)(y + j) * DMODEL + x];
    __syncthreads();
    int x2 = blockIdx.y * 32 + threadIdx.x;
    int y2 = blockIdx.x * 32 + threadIdx.y;
#pragma unroll
    for (int j = 0; j < 32; j += 8)
        dst[(size_t)(y2 + j) * DMODEL + x2] = __float2bfloat16(t[threadIdx.x][threadIdx.y + j]);
}

// ---------------- bf16 GEMM: out = A[M,1024] @ Wt^T + bias --------------------
// BM=BN=128, BK=32. 8 warps (4m x 2n), warp tile 32x64, mma m16n8k16.
// All fragments via ldmatrix.x4 (20-word row pad -> conflict-free phases).
#define GBM 128
#define GBN 128
#define GBK 32
#define GLD 20                 // words per smem row (16 data + 4 pad)
#define GROWB (GLD*4)          // 80 bytes per row
#define GSTG (128*GLD)         // words per stage

__global__ __launch_bounds__(256, 2) void gemm_bf16(
    const __nv_bfloat16* __restrict__ A, const __nv_bfloat16* __restrict__ Bt,
    const float* __restrict__ bias, void* __restrict__ outp,
    int split_heads, float oscale)
{
    __shared__ __align__(16) uint32_t gsm[4 * GSTG];   // A0,A1,B0,B1 = 40KB
    const uint32_t sb = smem_u32(gsm);

    const int tid  = threadIdx.x;
    const int lane = tid & 31;
    const int warp = tid >> 5;
    const int wm   = warp >> 1;          // 0..3
    const int wn   = warp & 1;           // 0..1
    const int m0   = blockIdx.y * GBM;
    const int n0   = blockIdx.x * GBN;

    const __nv_bfloat16* Abase = A  + (size_t)m0 * DMODEL;
    const __nv_bfloat16* Bbase = Bt + (size_t)n0 * DMODEL;

    // per-lane ldmatrix byte offsets (within a stage)
    const int lr = lane & 7;
    const uint32_t aoff = (uint32_t)((((lane >> 3) & 1) * 8 + lr) * GROWB
                                     + ((lane >> 4) & 1) * 16);
    const uint32_t boff = (uint32_t)((((lane >> 4) & 1) * 8 + lr) * GROWB
                                     + ((lane >> 3) & 1) * 16);

    float acc[2][8][4];
#pragma unroll
    for (int im = 0; im < 2; im++)
#pragma unroll
        for (int in = 0; in < 8; in++)
#pragma unroll
            for (int k = 0; k < 4; k++) acc[im][in][k] = 0.f;

#define GLOAD(c, s) do {                                                       \
        _Pragma("unroll")                                                      \
        for (int i_ = 0; i_ < 2; i_++) {                                       \
            int idx_ = tid + i_ * 256;                                         \
            int r_ = idx_ >> 2, q_ = idx_ & 3;                                 \
            cpasync16(sb + ((s) * GSTG + r_ * GLD + q_ * 4) * 4,               \
                      Abase + (size_t)r_ * DMODEL + (c) * GBK + q_ * 8);       \
        }                                                                      \
        _Pragma("unroll")                                                      \
        for (int i_ = 0; i_ < 2; i_++) {                                       \
            int idx_ = tid + i_ * 256;                                         \
            int r_ = idx_ >> 2, q_ = idx_ & 3;                                 \
            cpasync16(sb + ((2 + (s)) * GSTG + r_ * GLD + q_ * 4) * 4,         \
                      Bbase + (size_t)r_ * DMODEL + (c) * GBK + q_ * 8);       \
        }                                                                      \
        cp_commit();                                                           \
    } while (0)

    GLOAD(0, 0);
    const int NCH = DMODEL / GBK;   // 32
    for (int c = 0; c < NCH; c++) {
        const int bsl = c & 1;
        cp_wait0();
        __syncthreads();
        if (c + 1 < NCH) GLOAD(c + 1, 1 - bsl);

        const uint32_t abase = sb + (uint32_t)(bsl * GSTG * 4)
                             + (uint32_t)(wm * 32) * GROWB + aoff;
        const uint32_t bbase = sb + (uint32_t)((2 + bsl) * GSTG * 4)
                             + (uint32_t)(wn * 64) * GROWB + boff;

#pragma unroll
        for (int ks = 0; ks < 2; ks++) {
            uint32_t a[2][4];
            ldsm_x4(a[0][0], a[0][1], a[0][2], a[0][3], abase + ks * 32);
            ldsm_x4(a[1][0], a[1][1], a[1][2], a[1][3], abase + 16 * GROWB + ks * 32);
#pragma unroll
            for (int p = 0; p < 4; p++) {
                uint32_t b00, b01, b10, b11;
                ldsm_x4(b00, b01, b10, b11, bbase + p * 16 * GROWB + ks * 32);
                mma_bf16(acc[0][2 * p],     a[0], b00, b01);
                mma_bf16(acc[0][2 * p + 1], a[0], b10, b11);
                mma_bf16(acc[1][2 * p],     a[1], b00, b01);
                mma_bf16(acc[1][2 * p + 1], a[1], b10, b11);
            }
        }
        __syncthreads();
    }

    // epilogue
#pragma unroll
    for (int im = 0; im < 2; im++) {
#pragma unroll
        for (int in = 0; in < 8; in++) {
            int row = m0 + wm * 32 + im * 16 + (lane >> 2);
            int col = n0 + wn * 64 + in * 8 + 2 * (lane & 3);
            float b0 = bias[col], b1 = bias[col + 1];
            float v00 = (acc[im][in][0] + b0) * oscale;
            float v01 = (acc[im][in][1] + b1) * oscale;
            float v10 = (acc[im][in][2] + b0) * oscale;
            float v11 = (acc[im][in][3] + b1) * oscale;
            if (split_heads) {
                __nv_bfloat16* ob = (__nv_bfloat16*)outp;
                int bb = row >> 11, s = row & (SEQ - 1);
                int hh = col >> 6,  d = col & 63;
                size_t base = (((size_t)(bb * NHEAD + hh) * SEQ + s) * DHEAD + d);
                *(uint32_t*)(ob + base)              = pack_bf16(v00, v01);
                *(uint32_t*)(ob + base + 8 * DHEAD)  = pack_bf16(v10, v11);
            } else {
                float* of = (float*)outp;
                size_t base = (size_t)row * DMODEL + col;
                *(float2*)(of + base)                       = make_float2(v00, v01);
                *(float2*)(of + base + (size_t)8 * DMODEL)  = make_float2(v10, v11);
            }
        }
    }
}

// ---------------- flash attention, bf16 mma, register-resident P --------------
// CTA: (b,h,128-query tile), 8 warps x 16 rows, full 64-key width per warp.
// K fragments via ldmatrix.x4 (stride 144B -> conflict-free), V via x4.trans.
#define AQ 128
#define AROW 144                 // bytes per K/V smem row (128 data + 16 pad)
#define KOFF(s) ((s) * 9216)
#define VOFF(s) (18432 + (s) * 9216)
#define MOFF(s) (36864 + (s) * 256)
#define ASMEM 37376

__global__ __launch_bounds__(256, 2) void attn_kernel(
    const __nv_bfloat16* __restrict__ Q, const __nv_bfloat16* __restrict__ K,
    const __nv_bfloat16* __restrict__ V, const float* __restrict__ mask,
    __nv_bfloat16* __restrict__ ctx)
{
    __shared__ __align__(16) uint8_t smr[ASMEM];
    const uint32_t sb = smem_u32(smr);

    const int tid  = threadIdx.x;
    const int lane = tid & 31;
    const int warp = tid >> 5;

    const int q0 = blockIdx.x * AQ;
    const int h  = blockIdx.y;
    const int b  = blockIdx.z;

    const __nv_bfloat16* Qp = Q + (((size_t)(b * NHEAD + h) * SEQ + q0) * DHEAD);
    const __nv_bfloat16* Kp = K + ((size_t)(b * NHEAD + h) * SEQ) * DHEAD;
    const __nv_bfloat16* Vp = V + ((size_t)(b * NHEAD + h) * SEQ) * DHEAD;
    const float* Mp = mask + (size_t)b * SEQ;

#define APREFETCH(kt, s) do {                                                  \
        const int key0_ = (kt) * 64;                                           \
        _Pragma("unroll")                                                      \
        for (int i_ = 0; i_ < 2; i_++) {                                       \
            int idx_ = tid + i_ * 256;                                         \
            int r_ = idx_ >> 3, q_ = idx_ & 7;                                 \
            cpasync16(sb + KOFF(s) + r_ * AROW + q_ * 16,                      \
                      Kp + (size_t)(key0_ + r_) * DHEAD + q_ * 8);             \
        }                                                                      \
        _Pragma("unroll")                                                      \
        for (int i_ = 0; i_ < 2; i_++) {                                       \
            int idx_ = tid + i_ * 256;                                         \
            int r_ = idx_ >> 3, q_ = idx_ & 7;                                 \
            cpasync16(sb + VOFF(s) + r_ * AROW + q_ * 16,                      \
                      Vp + (size_t)(key0_ + r_) * DHEAD + q_ * 8);             \
        }                                                                      \
        if (tid < 16)                                                          \
            cpasync16(sb + MOFF(s) + tid * 16, Mp + key0_ + tid * 4);          \
        cp_commit();                                                           \
    } while (0)

    APREFETCH(0, 0);

    // ---- Q fragments straight from gmem (bf16 pairs are mma-native)
    uint32_t qf[4][4];
    {
        const int r = warp * 16 + (lane >> 2);
#pragma unroll
        for (int ks = 0; ks < 4; ks++) {
            int k0 = ks * 16 + 2 * (lane & 3);
            qf[ks][0] = *(const uint32_t*)(Qp + (size_t)r * DHEAD + k0);
            qf[ks][1] = *(const uint32_t*)(Qp + (size_t)(r + 8) * DHEAD + k0);
            qf[ks][2] = *(const uint32_t*)(Qp + (size_t)r * DHEAD + k0 + 8);
            qf[ks][3] = *(const uint32_t*)(Qp + (size_t)(r + 8) * DHEAD + k0 + 8);
        }
    }

    float m0 = -1e30f, m1 = -1e30f, l0 = 0.f, l1 = 0.f;
    float oacc[8][4];
#pragma unroll
    for (int in = 0; in < 8; in++)
#pragma unroll
        for (int k = 0; k < 4; k++) oacc[in][k] = 0.f;

    // per-lane ldmatrix offsets
    const int lr = lane & 7;
    // K b-frags: matrices [in0/klo, in0/khi, in1/klo, in1/khi]
    const uint32_t kloff = (uint32_t)((((lane >> 4) & 1) * 8 + lr) * AROW
                                      + ((lane >> 3) & 1) * 16);
    // V (trans): 4 matrices spanning 16 key-rows x 16 dh-cols
    const uint32_t vlaneoff =
        ((lane & 7) + ((lane & 8) ? 8u : 0u)) * AROW + ((lane & 16) ? 16u : 0u);

    for (int kt = 0; kt < SEQ / 64; kt++) {
        const int bsl = kt & 1;
        cp_wait0();
        __syncthreads();
        if (kt + 1 < SEQ / 64) APREFETCH(kt + 1, 1 - bsl);

        const float*   msk   = (const float*)(smr + MOFF(bsl));
        const uint32_t kbase = sb + KOFF(bsl) + kloff;
        const uint32_t vbase = sb + VOFF(bsl);

        // ---- S = Q @ K^T  (16 x 64 per warp, registers; K via ldmatrix)
        float sacc[8][4];
#pragma unroll
        for (int in = 0; in < 8; in++)
#pragma unroll
            for (int k = 0; k < 4; k++) sacc[in][k] = 0.f;

#pragma unroll
        for (int ks = 0; ks < 4; ks++) {
#pragma unroll
            for (int p = 0; p < 4; p++) {
                uint32_t b00, b01, b10, b11;
                ldsm_x4(b00, b01, b10, b11, kbase + p * (16 * AROW) + ks * 32);
                mma_bf16(sacc[2 * p],     qf[ks], b00, b01);
                mma_bf16(sacc[2 * p + 1], qf[ks], b10, b11);
            }
        }

        // ---- mask + register online softmax
        float mx0 = -1e30f, mx1 = -1e30f;
#pragma unroll
        for (int in = 0; in < 8; in++) {
            int c = in * 8 + 2 * (lane & 3);
            float mv0 = msk[c], mv1 = msk[c + 1];
            sacc[in][0] += mv0; sacc[in][1] += mv1;
            sacc[in][2] += mv0; sacc[in][3] += mv1;
            mx0 = fmaxf(mx0, fmaxf(sacc[in][0], sacc[in][1]));
            mx1 = fmaxf(mx1, fmaxf(sacc[in][2], sacc[in][3]));
        }
        mx0 = fmaxf(mx0, __shfl_xor_sync(0xffffffffu, mx0, 1));
        mx0 = fmaxf(mx0, __shfl_xor_sync(0xffffffffu, mx0, 2));
        mx1 = fmaxf(mx1, __shfl_xor_sync(0xffffffffu, mx1, 1));
        mx1 = fmaxf(mx1, __shfl_xor_sync(0xffffffffu, mx1, 2));

        const float mn0 = fmaxf(m0, mx0), mn1 = fmaxf(m1, mx1);
        const float a0 = __expf(m0 - mn0), a1 = __expf(m1 - mn1);
        m0 = mn0; m1 = mn1;

        uint32_t pk[8][2];
        float rs0 = 0.f, rs1 = 0.f;
#pragma unroll
        for (int in = 0; in < 8; in++) {
            float p0 = __expf(sacc[in][0] - mn0);
            float p1 = __expf(sacc[in][1] - mn0);
            float p2 = __expf(sacc[in][2] - mn1);
            float p3 = __expf(sacc[in][3] - mn1);
            rs0 += p0 + p1; rs1 += p2 + p3;
            pk[in][0] = pack_bf16(p0, p1);
            pk[in][1] = pack_bf16(p2, p3);
        }
        rs0 += __shfl_xor_sync(0xffffffffu, rs0, 1);
        rs0 += __shfl_xor_sync(0xffffffffu, rs0, 2);
        rs1 += __shfl_xor_sync(0xffffffffu, rs1, 1);
        rs1 += __shfl_xor_sync(0xffffffffu, rs1, 2);
        l0 = l0 * a0 + rs0;
        l1 = l1 * a1 + rs1;

#pragma unroll
        for (int in = 0; in < 8; in++) {
            oacc[in][0] *= a0; oacc[in][1] *= a0;
            oacc[in][2] *= a1; oacc[in][3] *= a1;
        }

        // ---- O += P @ V   (A-frags from pk registers; B via ldmatrix.trans)
#pragma unroll
        for (int ks = 0; ks < 4; ks++) {
            uint32_t a[4] = { pk[2 * ks][0], pk[2 * ks][1],
                              pk[2 * ks + 1][0], pk[2 * ks + 1][1] };
            uint32_t vk = vbase + (uint32_t)(ks * 16) * AROW + vlaneoff;
#pragma unroll
            for (int gi = 0; gi < 4; gi++) {
                uint32_t b0a, b1a, b0b, b1b;
                ldsm_x4_t(b0a, b1a, b0b, b1b, vk + gi * 32);
                mma_bf16(oacc[2 * gi],     a, b0a, b1a);
                mma_bf16(oacc[2 * gi + 1], a, b0b, b1b);
            }
        }
    }

    // ---- finalize: /l, write ctx bf16 [B,S,D]  (d = h*64 + col)
    {
        const int rp = warp * 16 + (lane >> 2);
        const float il0 = 1.f / l0, il1 = 1.f / l1;
#pragma unroll
        for (int in = 0; in < 8; in++) {
            int c = in * 8 + 2 * (lane & 3);
            size_t base = ((size_t)b * SEQ + q0 + rp) * DMODEL + h * DHEAD + c;
            *(uint32_t*)(ctx + base) =
                pack_bf16(oacc[in][0] * il0, oacc[in][1] * il0);
            *(uint32_t*)(ctx + base + (size_t)8 * DMODEL) =
                pack_bf16(oacc[in][2] * il1, oacc[in][3] * il1);
        }
    }
}

// ---------------- residual + LayerNorm ---------------------------------------
__global__ __launch_bounds__(256) void ln_kernel(
    const float* __restrict__ hbuf, const float* __restrict__ x,
    const float* __restrict__ gamma, const float* __restrict__ beta,
    float* __restrict__ out)
{
    const int row = blockIdx.x;
    const int tid = threadIdx.x;
    const int lane = tid & 31, warp = tid >> 5;

    const float4* hp = (const float4*)(hbuf + (size_t)row * DMODEL);
    const float4* xp = (const float4*)(x + (size_t)row * DMODEL);
    float4 hv = hp[tid], xv = xp[tid];
    float4 y = make_float4(hv.x + xv.x, hv.y + xv.y, hv.z + xv.z, hv.w + xv.w);

    float s  = y.x + y.y + y.z + y.w;
    float sq = y.x * y.x + y.y * y.y + y.z * y.z + y.w * y.w;
#pragma unroll
    for (int o = 16; o; o >>= 1) {
        s  += __shfl_xor_sync(0xffffffffu, s, o);
        sq += __shfl_xor_sync(0xffffffffu, sq, o);
    }
    __shared__ float ss[8], ssq[8];
    if (lane == 0) { ss[warp] = s; ssq[warp] = sq; }
    __syncthreads();
    if (warp == 0) {
        s  = (lane < 8) ? ss[lane]  : 0.f;
        sq = (lane < 8) ? ssq[lane] : 0.f;
#pragma unroll
        for (int o = 4; o; o >>= 1) {
            s  += __shfl_xor_sync(0xffffffffu, s, o);
            sq += __shfl_xor_sync(0xffffffffu, sq, o);
        }
        if (lane == 0) { ss[0] = s; ssq[0] = sq; }
    }
    __syncthreads();
    s = ss[0]; sq = ssq[0];

    const float mu   = s * (1.f / DMODEL);
    const float var  = sq * (1.f / DMODEL) - mu * mu;
    const float rstd = rsqrtf(var + 1e-12f);

    float4 g = ((const float4*)gamma)[tid];
    float4 bt = ((const float4*)beta)[tid];
    float4 o;
    o.x = (y.x - mu) * rstd * g.x + bt.x;
    o.y = (y.y - mu) * rstd * g.y + bt.y;
    o.z = (y.z - mu) * rstd * g.z + bt.z;
    o.w = (y.w - mu) * rstd * g.w + bt.w;
    ((float4*)(out + (size_t)row * DMODEL))[tid] = o;
}

// ---------------- launch ------------------------------------------------------
extern "C" void kernel_launch(void* const* d_in, const int* in_sizes, int n_in,
                              void* d_out, int out_size)
{
    const float* x    = (const float*)d_in[0];
    const float* mask = (const float*)d_in[1];
    const float* Wq   = (const float*)d_in[2];
    const float* bq   = (const float*)d_in[3];
    const float* Wk   = (const float*)d_in[4];
    const float* bk   = (const float*)d_in[5];
    const float* Wv   = (const float*)d_in[6];
    const float* bv   = (const float*)d_in[7];
    const float* Wo   = (const float*)d_in[8];
    const float* bo   = (const float*)d_in[9];
    const float* gam  = (const float*)d_in[10];
    const float* bet  = (const float*)d_in[11];
    float* out = (float*)d_out;

    __nv_bfloat16 *pxb, *pQ, *pK, *pV, *pC, *pWt;
    float *pH;
    cudaGetSymbolAddress((void**)&pxb, g_xb);
    cudaGetSymbolAddress((void**)&pQ,  g_Qb);
    cudaGetSymbolAddress((void**)&pK,  g_Kb);
    cudaGetSymbolAddress((void**)&pV,  g_Vb);
    cudaGetSymbolAddress((void**)&pC,  g_ctxb);
    cudaGetSymbolAddress((void**)&pWt, g_Wtb);
    cudaGetSymbolAddress((void**)&pH,  g_h);
    __nv_bfloat16* Wtq = pWt;
    __nv_bfloat16* Wtk = pWt + (size_t)DMODEL * DMODEL;
    __nv_bfloat16* Wtv = pWt + (size_t)2 * DMODEL * DMODEL;
    __nv_bfloat16* Wto = pWt + (size_t)3 * DMODEL * DMODEL;

    cvt_kernel<<<MTOT * DMODEL / 4 / 256, 256>>>(x, (__nv_bfloat162*)pxb);
    tr_kernel<<<dim3(32, 32, 4), dim3(32, 8)>>>(Wq, Wk, Wv, Wo, pWt);

    dim3 ggrid(DMODEL / GBN, MTOT / GBM);   // (8, 64)
    gemm_bf16<<<ggrid, 256>>>(pxb, Wtq, bq, pQ, 1, 0.125f);
    gemm_bf16<<<ggrid, 256>>>(pxb, Wtk, bk, pK, 1, 1.0f);
    gemm_bf16<<<ggrid, 256>>>(pxb, Wtv, bv, pV, 1, 1.0f);

    attn_kernel<<<dim3(SEQ / AQ, NHEAD, BATCH), 256>>>(pQ, pK, pV, mask, pC);

    gemm_bf16<<<ggrid, 256>>>(pC, Wto, bo, pH, 0, 1.0f);
    ln_kernel<<<MTOT, 256>>>(pH, x, gam, bet, out);
}